// round 17
// baseline (speedup 1.0000x reference)
#include <cuda_runtime.h>

// xg scratch: [B=32][T=2048][4H=1024] fp32 = 256 MB
__device__ float g_xg[32ull * 2048ull * 1024ull];

// ---------------- f32x2 helpers (sm_103a packed fp32) ----------------
__device__ __forceinline__ void fma2(unsigned long long &acc,
                                     unsigned long long a,
                                     unsigned long long b) {
    asm("fma.rn.f32x2 %0, %1, %2, %0;" : "+l"(acc) : "l"(a), "l"(b));
}
__device__ __forceinline__ unsigned long long splat2(float x) {
    unsigned long long r;
    unsigned xu = __float_as_uint(x);
    asm("mov.b64 %0, {%1, %1};" : "=l"(r) : "r"(xu));
    return r;
}
__device__ __forceinline__ float hadd2(unsigned long long v) {
    float lo, hi;
    asm("mov.b64 {%0, %1}, %2;" : "=f"(lo), "=f"(hi) : "l"(v));
    return lo + hi;
}
__device__ __forceinline__ float sigf(float x) {
    return __fdividef(1.f, 1.f + __expf(-x));
}
__device__ __forceinline__ float tanhf_fast(float x) {
    return __fdividef(2.f, 1.f + __expf(-2.f * x)) - 1.f;
}
__device__ __forceinline__ unsigned smem_u32(const void* p) {
    return (unsigned)__cvta_generic_to_shared(p);
}

// mbarrier primitives
__device__ __forceinline__ void mbar_init(unsigned mbar, unsigned cnt) {
    asm volatile("mbarrier.init.shared.b64 [%0], %1;" :: "r"(mbar), "r"(cnt) : "memory");
}
__device__ __forceinline__ void mbar_arm_tx(unsigned mbar, unsigned bytes) {
    asm volatile("mbarrier.arrive.expect_tx.shared.b64 _, [%0], %1;"
                 :: "r"(mbar), "r"(bytes) : "memory");
}
__device__ __forceinline__ void mbar_wait(unsigned mbar, unsigned parity) {
    unsigned done;
    asm volatile(
        "{\n\t.reg .pred p;\n\t"
        "mbarrier.try_wait.parity.acquire.cta.shared::cta.b64 p, [%1], %2;\n\t"
        "selp.b32 %0, 1, 0, p;\n\t}"
        : "=r"(done) : "r"(mbar), "r"(parity) : "memory");
    while (!done) {
        asm volatile(
            "{\n\t.reg .pred p;\n\t"
            "mbarrier.try_wait.parity.acquire.cta.shared::cta.b64 p, [%1], %2, 0x989680;\n\t"
            "selp.b32 %0, 1, 0, p;\n\t}"
            : "=r"(done) : "r"(mbar), "r"(parity) : "memory");
    }
}
// 16-byte remote store + tx-signal (data delivery IS the sync)
__device__ __forceinline__ void st_async_v4(unsigned laddr, unsigned lbar,
                                            unsigned rank, float4 v) {
    asm volatile(
        "{\n\t.reg .b32 ra, rb;\n\t"
        "mapa.shared::cluster.u32 ra, %0, %2;\n\t"
        "mapa.shared::cluster.u32 rb, %1, %2;\n\t"
        "st.async.shared::cluster.mbarrier::complete_tx::bytes.v4.b32 "
        "[ra], {%3, %4, %5, %6}, [rb];\n\t}"
        :: "r"(laddr), "r"(lbar), "r"(rank),
           "r"(__float_as_uint(v.x)), "r"(__float_as_uint(v.y)),
           "r"(__float_as_uint(v.z)), "r"(__float_as_uint(v.w)) : "memory");
}

// =====================================================================
// Phase 1: xg[m][g] = relu(x)[m][:] . W_ih[g][:] + b_ih[g] + b_hh[g]
// (unchanged — FMA-bound, not the bottleneck)
// =====================================================================
__global__ __launch_bounds__(256, 2) void p1_gemm(
    const float* __restrict__ x, const float* __restrict__ Wih,
    const float* __restrict__ bih, const float* __restrict__ bhh)
{
    __shared__ __align__(16) float Asm[16][132];  // [k][m]
    __shared__ __align__(16) float Wsm[16][132];  // [k][g]

    const int t  = threadIdx.x;
    const int tx = t & 15, ty = t >> 4;
    const int mb = blockIdx.y * 128;
    const int gb = blockIdx.x * 128;

    unsigned long long acc[4][8];
    #pragma unroll
    for (int p = 0; p < 4; p++)
        #pragma unroll
        for (int g = 0; g < 8; g++) acc[p][g] = 0ull;

    for (int kb = 0; kb < 256; kb += 16) {
        #pragma unroll
        for (int i = 0; i < 2; i++) {
            int idx = t + i * 256;
            int m   = idx >> 2;
            int kc  = (idx & 3) << 2;
            float4 av = *(const float4*)(x + (size_t)(mb + m) * 256 + kb + kc);
            Asm[kc + 0][m] = fmaxf(av.x, 0.f);
            Asm[kc + 1][m] = fmaxf(av.y, 0.f);
            Asm[kc + 2][m] = fmaxf(av.z, 0.f);
            Asm[kc + 3][m] = fmaxf(av.w, 0.f);
            float4 wv = *(const float4*)(Wih + (size_t)(gb + m) * 256 + kb + kc);
            Wsm[kc + 0][m] = wv.x;
            Wsm[kc + 1][m] = wv.y;
            Wsm[kc + 2][m] = wv.z;
            Wsm[kc + 3][m] = wv.w;
        }
        __syncthreads();
        #pragma unroll
        for (int k = 0; k < 16; k++) {
            ulonglong2 a01 = *(const ulonglong2*)&Asm[k][ty * 8];
            ulonglong2 a23 = *(const ulonglong2*)&Asm[k][ty * 8 + 4];
            float4 w0 = *(const float4*)&Wsm[k][tx * 8];
            float4 w1 = *(const float4*)&Wsm[k][tx * 8 + 4];
            float wf[8] = {w0.x, w0.y, w0.z, w0.w, w1.x, w1.y, w1.z, w1.w};
            #pragma unroll
            for (int g = 0; g < 8; g++) {
                unsigned long long ws = splat2(wf[g]);
                fma2(acc[0][g], a01.x, ws);
                fma2(acc[1][g], a01.y, ws);
                fma2(acc[2][g], a23.x, ws);
                fma2(acc[3][g], a23.y, ws);
            }
        }
        __syncthreads();
    }

    float bs[8];
    {
        const float4* bi = (const float4*)(bih + gb + tx * 8);
        const float4* bh = (const float4*)(bhh + gb + tx * 8);
        float4 b0 = bi[0], b1 = bi[1], c0 = bh[0], c1 = bh[1];
        bs[0] = b0.x + c0.x; bs[1] = b0.y + c0.y; bs[2] = b0.z + c0.z; bs[3] = b0.w + c0.w;
        bs[4] = b1.x + c1.x; bs[5] = b1.y + c1.y; bs[6] = b1.z + c1.z; bs[7] = b1.w + c1.w;
    }
    #pragma unroll
    for (int p = 0; p < 4; p++) {
        float lo[8], hi[8];
        #pragma unroll
        for (int g = 0; g < 8; g++) {
            float l, h;
            asm("mov.b64 {%0, %1}, %2;" : "=f"(l), "=f"(h) : "l"(acc[p][g]));
            lo[g] = l + bs[g];
            hi[g] = h + bs[g];
        }
        size_t m0 = (size_t)(mb + ty * 8 + 2 * p);
        float* r0 = g_xg + m0 * 1024 + gb + tx * 8;
        float* r1 = r0 + 1024;
        *(float4*)(r0)     = make_float4(lo[0], lo[1], lo[2], lo[3]);
        *(float4*)(r0 + 4) = make_float4(lo[4], lo[5], lo[6], lo[7]);
        *(float4*)(r1)     = make_float4(hi[0], hi[1], hi[2], hi[3]);
        *(float4*)(r1 + 4) = make_float4(hi[4], hi[5], hi[6], hi[7]);
    }
}

// =====================================================================
// Phase 2: recurrence. 512 threads/CTA, 4-way k-split + 4-way split
// source-group barriers. 16 clusters x 8 CTAs; cluster c handles
// batches {2c, 2c+1}. CTA rank r owns h-indices [32r,32r+32).
// h buffer rank-major: h_lin[buf][r*64 + b*32 + j].
// Thread (t): quarter kh2 = t>>7 owns k-range [kh2*64, kh2*64+64)
// = source ranks {2*kh2, 2*kh2+1}; row = t&127 is the gate row.
// Barrier word g is signaled by ranks {2g, 2g+1} (512 B/phase) and
// waited ONLY by quarter kh2==g -> fine-grained skew absorption.
// =====================================================================
__global__ __launch_bounds__(512, 1) __cluster_dims__(8, 1, 1)
void p2_lstm(const float* __restrict__ Whh, float* __restrict__ out)
{
    __shared__ __align__(16) float h_lin[2][512];       // [buf][r*64+b*32+j]
    __shared__ __align__(16) float ring[4][256];        // xg [slot][b*128+gt*32+j]
    __shared__ __align__(8)  float red_sm[4][128][2];   // [kh2][row][batch]
    __shared__ __align__(8)  unsigned long long barr[8]; // [group][phase]

    unsigned rank;
    asm("mov.u32 %0, %%cluster_ctarank;" : "=r"(rank));
    const int t    = threadIdx.x;
    const int row  = t & 127;
    const int kh2  = t >> 7;                 // k-quarter 0..3
    const int gt   = row >> 5;
    const int j    = row & 31;
    const int G    = gt * 256 + (int)rank * 32 + j;   // global gate row
    const int b0   = (blockIdx.x >> 3) * 2;

    // persistent weights: 32 x f32x2 in registers (k = kh2*64 + 2i)
    unsigned long long w2[32];
    {
        const unsigned long long* wp =
            (const unsigned long long*)(Whh + (size_t)G * 256 + kh2 * 64);
        #pragma unroll
        for (int i = 0; i < 32; i++) w2[i] = wp[i];
    }

    for (int i = t; i < 1024; i += 512) ((float*)h_lin)[i] = 0.f;

    // xg ring loader: threads t<256 cover (b=t>>7, g2=(t>>5)&3, j2=t&31)
    const float* xg_ld = g_xg
        + (size_t)(b0 + ((t >> 7) & 1)) * 2048 * 1024
        + (size_t)(((t >> 5) & 3) * 256 + (int)rank * 32 + (t & 31));
    float pend = 0.f;
    if (t < 256) {
        ring[0][t] = xg_ld[0];
        ring[1][t] = xg_ld[1024];
        pend = xg_ld[2 * 1024];
    }

    unsigned barw[8];
    #pragma unroll
    for (int i = 0; i < 8; i++) barw[i] = smem_u32(&barr[i]);
    if (t == 0)
        #pragma unroll
        for (int i = 0; i < 8; i++) mbar_init(barw[i], 1);
    __syncthreads();
    asm volatile("barrier.cluster.arrive.aligned;" ::: "memory");
    asm volatile("barrier.cluster.wait.aligned;"   ::: "memory");
    if (t == 0)
        #pragma unroll
        for (int i = 0; i < 8; i++) mbar_arm_tx(barw[i], 512);

    const int ub = t >> 5, uj = t & 31;              // update mapping (t<64)
    float c_state = 0.f;
    unsigned ph0 = 0, ph1 = 0;                       // my group's parities
    const unsigned mybar0 = barw[kh2 * 2 + 0];       // wait targets (group kh2)
    const unsigned mybar1 = barw[kh2 * 2 + 1];
    // senders signal the word of THEIR rank group at each destination
    const int sgi = ((int)rank >> 1) * 2;
    const unsigned sbar0 = barw[sgi + 0];
    const unsigned sbar1 = barw[sgi + 1];
    float* out_p = out + (size_t)(b0 + ub) * 2048 * 256 + (int)rank * 32 + uj;

    for (int step = 0; step < 2048; step++) {
        const int rb = step & 1;
        const int wb = rb ^ 1;

        if (step > 0) {
            // each quarter waits only for ITS two source ranks' data;
            // re-arm by one thread per group (t = 0,128,256,384)
            if (rb) {
                mbar_wait(mybar1, ph1); ph1 ^= 1;
                if ((t & 127) == 0) mbar_arm_tx(mybar1, 512);
            } else {
                mbar_wait(mybar0, ph0); ph0 ^= 1;
                if ((t & 127) == 0) mbar_arm_tx(mybar0, 512);
            }
        }

        // xg pipeline: store step+2's data (loaded last iter), load step+3
        if (t < 256) {
            ring[(step + 2) & 3][t] = pend;
            int ps = step + 3; if (ps > 2047) ps = 2047;
            pend = xg_ld[(size_t)ps * 1024];
        }

        // ---- matvec: 2 batches x 64-k quarter (2 rank chunks) ----
        unsigned long long a0a = 0ull, a0b = 0ull, a1a = 0ull, a1b = 0ull;
        #pragma unroll
        for (int c = 0; c < 2; c++) {
            const ulonglong2* hp0 =
                (const ulonglong2*)&h_lin[rb][(kh2 * 2 + c) * 64];
            const ulonglong2* hp1 =
                (const ulonglong2*)&h_lin[rb][(kh2 * 2 + c) * 64 + 32];
            #pragma unroll
            for (int q = 0; q < 8; q++) {
                ulonglong2 hv0 = hp0[q];
                ulonglong2 hv1 = hp1[q];
                int wi = c * 16 + 2 * q;
                fma2(a0a, w2[wi],     hv0.x);
                fma2(a0b, w2[wi + 1], hv0.y);
                fma2(a1a, w2[wi],     hv1.x);
                fma2(a1b, w2[wi + 1], hv1.y);
            }
        }
        red_sm[kh2][row][0] = hadd2(a0a) + hadd2(a0b);
        red_sm[kh2][row][1] = hadd2(a1a) + hadd2(a1b);
        __syncthreads();   // orders h_lin[rb] reads + red/ring writes

        // ---- fused activation + c/h update (64 threads, 2 full warps) ----
        if (t < 64) {
            const float* xr = &ring[step & 3][ub * 128 + uj];
            float gi = red_sm[0][      uj][ub] + red_sm[1][      uj][ub]
                     + red_sm[2][      uj][ub] + red_sm[3][      uj][ub] + xr[0];
            float gf = red_sm[0][ 32 + uj][ub] + red_sm[1][ 32 + uj][ub]
                     + red_sm[2][ 32 + uj][ub] + red_sm[3][ 32 + uj][ub] + xr[32];
            float gg = red_sm[0][ 64 + uj][ub] + red_sm[1][ 64 + uj][ub]
                     + red_sm[2][ 64 + uj][ub] + red_sm[3][ 64 + uj][ub] + xr[64];
            float go = red_sm[0][ 96 + uj][ub] + red_sm[1][ 96 + uj][ub]
                     + red_sm[2][ 96 + uj][ub] + red_sm[3][ 96 + uj][ub] + xr[96];
            float iv = sigf(gi);
            float fv = sigf(gf);
            float gv = tanhf_fast(gg);
            float ov = sigf(go);
            c_state = fv * c_state + iv * gv;
            float h = ov * tanhf_fast(c_state);

            // gather 4 consecutive h into lanes with uj%4==0 (warp-level)
            float4 hv;
            hv.x = h;
            hv.y = __shfl_down_sync(0xffffffffu, h, 1);
            hv.z = __shfl_down_sync(0xffffffffu, h, 2);
            hv.w = __shfl_down_sync(0xffffffffu, h, 3);

            if (step < 2047 && (uj & 3) == 0) {
                unsigned laddr = smem_u32(
                    &h_lin[wb][(int)rank * 64 + ub * 32 + (uj & ~3)]);
                unsigned lbar  = wb ? sbar1 : sbar0;
                #pragma unroll
                for (int r = 0; r < 8; r++) st_async_v4(laddr, lbar, r, hv);
            }
            out_p[(size_t)step * 256] = h;
        }
    }

    asm volatile("barrier.cluster.arrive.aligned;" ::: "memory");
    asm volatile("barrier.cluster.wait.aligned;"   ::: "memory");
}

// =====================================================================
extern "C" void kernel_launch(void* const* d_in, const int* in_sizes, int n_in,
                              void* d_out, int out_size) {
    (void)in_sizes; (void)n_in; (void)out_size;
    const float* x   = (const float*)d_in[0];
    const float* Wih = (const float*)d_in[1];
    const float* Whh = (const float*)d_in[2];
    const float* bih = (const float*)d_in[3];
    const float* bhh = (const float*)d_in[4];
    float* out = (float*)d_out;

    dim3 g1(8, 512);
    p1_gemm<<<g1, 256>>>(x, Wih, bih, bhh);
    p2_lstm<<<128, 512>>>(Whh, out);   // 16 clusters of 8 CTAs
}